// round 12
// baseline (speedup 1.0000x reference)
#include <cuda_runtime.h>
#include <math.h>

#define NB    4
#define NRES  56
#define NTOK  3136            // 56*56
#define DIMF  384
#define TDF   192
#define MTOT  12544           // NB*NTOK

typedef unsigned long long ull;

// packed f32x2 helpers (sm_100+ PTX; FFMA2 is PTX-only per SASS_QUICKREF)
__device__ __forceinline__ ull ffma2(ull a, ull b, ull c) {
    ull d; asm("fma.rn.f32x2 %0, %1, %2, %3;" : "=l"(d) : "l"(a), "l"(b), "l"(c)); return d;
}
__device__ __forceinline__ ull fmul2(ull a, ull b) {
    ull d; asm("mul.rn.f32x2 %0, %1, %2;" : "=l"(d) : "l"(a), "l"(b)); return d;
}
__device__ __forceinline__ ull pack2(float x, float y) {
    ull r; asm("mov.b64 %0, {%1, %2};" : "=l"(r) : "f"(x), "f"(y)); return r;
}
__device__ __forceinline__ float2 unpack2(ull v) {
    float2 r; asm("mov.b64 {%0, %1}, %2;" : "=f"(r.x), "=f"(r.y) : "l"(v)); return r;
}
// exp2 approx (== __expf when logits are pre-scaled by log2(e))
__device__ __forceinline__ float exp2a(float x) {
    float y; asm("ex2.approx.ftz.f32 %0, %1;" : "=f"(y) : "f"(x)); return y;
}

// scratch (allocation-free rule: __device__ globals)
__device__ __align__(16) float g_tmp[(size_t)MTOT * DIMF];    // (m,384): 0..191 up, 192..383 dn
__device__ __align__(16) float g_qkv[(size_t)MTOT * 1152];    // (m,1152): 0..575 up qkv, 576..1151 dn qkv
__device__ __align__(16) float g_qT[(size_t)12 * 64 * NTOK];  // [(b*3+hd)][d][tok], pre-scaled Q_dn
__device__ __align__(16) float g_kT[(size_t)12 * 64 * NTOK];  // [(b*3+hd)][d][tok], K_dn

// ---------------------------------------------------------------------------
// GEMM1 (unchanged)
// ---------------------------------------------------------------------------
__global__ __launch_bounds__(256) void gemm1_kernel(
    const float* __restrict__ xa, const float* __restrict__ p1,
    const float* __restrict__ p2)
{
    __shared__ __align__(16) float As[16][260];
    __shared__ __align__(16) float Bs[16][68];
    int tid = threadIdx.x;
    int m0 = blockIdx.x * 256;
    int o0 = blockIdx.y * 64;
    const float* wb = (o0 < TDF) ? p1 : p2;
    int orow0 = (o0 < TDF) ? o0 : (o0 - TDF);

    int mm = m0 + tid;
    int bb = mm / NTOK;
    int nn = mm - bb * NTOK;
    const float* asrc = xa + (size_t)bb * DIMF * NTOK + nn;

    int b_ol = tid >> 2;
    int b_kq = tid & 3;

    ull acc2[8][4];
    #pragma unroll
    for (int i = 0; i < 8; i++)
        #pragma unroll
        for (int j = 0; j < 4; j++) acc2[i][j] = 0ull;

    int mr = (tid >> 4) * 16;
    int oc = (tid & 15) * 4;

    for (int k0 = 0; k0 < DIMF; k0 += 16) {
        #pragma unroll
        for (int k = 0; k < 16; k++)
            As[k][tid] = asrc[(size_t)(k0 + k) * NTOK];
        {
            float4 w4 = *(const float4*)(wb + (size_t)(orow0 + b_ol) * DIMF + k0 + b_kq * 4);
            Bs[b_kq*4+0][b_ol] = w4.x;
            Bs[b_kq*4+1][b_ol] = w4.y;
            Bs[b_kq*4+2][b_ol] = w4.z;
            Bs[b_kq*4+3][b_ol] = w4.w;
        }
        __syncthreads();
        #pragma unroll
        for (int k = 0; k < 16; k++) {
            const ulonglong2* ap = (const ulonglong2*)&As[k][mr];
            ull a2[8];
            #pragma unroll
            for (int q = 0; q < 4; q++) {
                ulonglong2 t = ap[q];
                a2[2*q] = t.x; a2[2*q+1] = t.y;
            }
            float4 bv = *(const float4*)&Bs[k][oc];
            ull b2[4];
            b2[0] = pack2(bv.x, bv.x); b2[1] = pack2(bv.y, bv.y);
            b2[2] = pack2(bv.z, bv.z); b2[3] = pack2(bv.w, bv.w);
            #pragma unroll
            for (int i = 0; i < 8; i++)
                #pragma unroll
                for (int j = 0; j < 4; j++)
                    acc2[i][j] = ffma2(a2[i], b2[j], acc2[i][j]);
        }
        __syncthreads();
    }
    #pragma unroll
    for (int i = 0; i < 8; i++) {
        float2 u0 = unpack2(acc2[i][0]);
        float2 u1 = unpack2(acc2[i][1]);
        float2 u2 = unpack2(acc2[i][2]);
        float2 u3 = unpack2(acc2[i][3]);
        *(float4*)(g_tmp + (size_t)(m0 + mr + 2*i)     * DIMF + o0 + oc) = make_float4(u0.x, u1.x, u2.x, u3.x);
        *(float4*)(g_tmp + (size_t)(m0 + mr + 2*i + 1) * DIMF + o0 + oc) = make_float4(u0.y, u1.y, u2.y, u3.y);
    }
}

// ---------------------------------------------------------------------------
// GEMM2 (unchanged)
// ---------------------------------------------------------------------------
__global__ __launch_bounds__(256) void gemm2_kernel(
    const float* __restrict__ wu, const float* __restrict__ wd)
{
    __shared__ __align__(16) float As[16][260];
    __shared__ __align__(16) float Bs[16][68];
    int tid = threadIdx.x;
    int m0 = blockIdx.x * 256;
    int o0 = blockIdx.y * 64;
    const float* wb; int orow0, koff;
    if (o0 < 576) { wb = wu; orow0 = o0;       koff = 0;   }
    else          { wb = wd; orow0 = o0 - 576; koff = TDF; }

    int b_ol = tid >> 2;
    int b_kq = tid & 3;

    ull acc2[8][4];
    #pragma unroll
    for (int i = 0; i < 8; i++)
        #pragma unroll
        for (int j = 0; j < 4; j++) acc2[i][j] = 0ull;

    int mr = (tid >> 4) * 16;
    int oc = (tid & 15) * 4;
    const float* asrc = g_tmp + (size_t)(m0 + tid) * DIMF + koff;

    for (int k0 = 0; k0 < TDF; k0 += 16) {
        #pragma unroll
        for (int q = 0; q < 4; q++) {
            float4 a4 = *(const float4*)(asrc + k0 + q * 4);
            As[q*4+0][tid] = a4.x;
            As[q*4+1][tid] = a4.y;
            As[q*4+2][tid] = a4.z;
            As[q*4+3][tid] = a4.w;
        }
        {
            float4 w4 = *(const float4*)(wb + (size_t)(orow0 + b_ol) * TDF + k0 + b_kq * 4);
            Bs[b_kq*4+0][b_ol] = w4.x;
            Bs[b_kq*4+1][b_ol] = w4.y;
            Bs[b_kq*4+2][b_ol] = w4.z;
            Bs[b_kq*4+3][b_ol] = w4.w;
        }
        __syncthreads();
        #pragma unroll
        for (int k = 0; k < 16; k++) {
            const ulonglong2* ap = (const ulonglong2*)&As[k][mr];
            ull a2[8];
            #pragma unroll
            for (int q = 0; q < 4; q++) {
                ulonglong2 t = ap[q];
                a2[2*q] = t.x; a2[2*q+1] = t.y;
            }
            float4 bv = *(const float4*)&Bs[k][oc];
            ull b2[4];
            b2[0] = pack2(bv.x, bv.x); b2[1] = pack2(bv.y, bv.y);
            b2[2] = pack2(bv.z, bv.z); b2[3] = pack2(bv.w, bv.w);
            #pragma unroll
            for (int i = 0; i < 8; i++)
                #pragma unroll
                for (int j = 0; j < 4; j++)
                    acc2[i][j] = ffma2(a2[i], b2[j], acc2[i][j]);
        }
        __syncthreads();
    }
    #pragma unroll
    for (int i = 0; i < 8; i++) {
        float2 u0 = unpack2(acc2[i][0]);
        float2 u1 = unpack2(acc2[i][1]);
        float2 u2 = unpack2(acc2[i][2]);
        float2 u3 = unpack2(acc2[i][3]);
        *(float4*)(g_qkv + (size_t)(m0 + mr + 2*i)     * 1152 + o0 + oc) = make_float4(u0.x, u1.x, u2.x, u3.x);
        *(float4*)(g_qkv + (size_t)(m0 + mr + 2*i + 1) * 1152 + o0 + oc) = make_float4(u0.y, u1.y, u2.y, u3.y);
    }
}

// ---------------------------------------------------------------------------
// ktrans (unchanged): Q pre-scaled by 0.125*log2e for base-2 softmax.
// ---------------------------------------------------------------------------
__global__ __launch_bounds__(256) void ktrans_kernel()
{
    int task = blockIdx.x * 256 + threadIdx.x;   // 602112 total
    int tok = task % NTOK;
    int r   = task / NTOK;    // 0..191
    int d4  = r & 15;
    int bh  = r >> 4;         // 0..11
    int b   = bh / 3;
    int hd  = bh - b * 3;

    const float qs = 0.18033688011112042f;   // 0.125 * log2(e)
    const float* src = g_qkv + (size_t)(b * NTOK + tok) * 1152 + 576 + hd * 64 + d4 * 4;
    float4 q4 = *(const float4*)src;            // Q_dn
    float4 k4 = *(const float4*)(src + TDF);    // K_dn
    size_t obase = ((size_t)bh * 64 + d4 * 4) * NTOK + tok;
    g_qT[obase + 0*NTOK] = q4.x * qs;
    g_qT[obase + 1*NTOK] = q4.y * qs;
    g_qT[obase + 2*NTOK] = q4.z * qs;
    g_qT[obase + 3*NTOK] = q4.w * qs;
    g_kT[obase + 0*NTOK] = k4.x;
    g_kT[obase + 1*NTOK] = k4.y;
    g_kT[obase + 2*NTOK] = k4.z;
    g_kT[obase + 3*NTOK] = k4.w;
}

// ---------------------------------------------------------------------------
// CSWin attention + fused LePE (unchanged from R10 passing version).
// ---------------------------------------------------------------------------
__global__ __launch_bounds__(256, 1) void cswin_kernel(
    const float* __restrict__ lw0, const float* __restrict__ lb0,
    const float* __restrict__ lw1, const float* __restrict__ lb1,
    float* __restrict__ out)
{
    extern __shared__ float smem[];
    float* sK    = smem;                    // [392][48]
    float* sV    = smem + 392 * 48;         // [392][48]
    float* swt   = smem + 2 * 392 * 48;     // [9][48]
    float* sbias = swt + 9 * 48;            // [48]

    int tid = threadIdx.x;
    int g  = blockIdx.x;
    int hd = blockIdx.y;
    int br = blockIdx.z;
    int wi = g & 7, b = g >> 3;
    int colq = br * 96 + hd * 48;

    {
        const float* lw = br ? lw1 : lw0;
        const float* lb = br ? lb1 : lb0;
        for (int idx = tid; idx < 432; idx += 256) {
            int nb = idx / 48, c = idx - nb * 48;
            swt[idx] = lw[(hd * 48 + c) * 9 + nb];
        }
        if (tid < 48) sbias[tid] = lb[hd * 48 + tid];
    }
    for (int idx = tid; idx < 392 * 12; idx += 256) {
        int j = idx / 12, c4 = idx - j * 12;
        int node = (br == 0) ? ((j / 7) * NRES + wi * 7 + (j % 7)) : (wi * 392 + j);
        const float* base = g_qkv + (size_t)(b * NTOK + node) * 1152 + colq;
        ((float4*)(sK + j * 48))[c4] = ((const float4*)(base + TDF))[c4];
        ((float4*)(sV + j * 48))[c4] = ((const float4*)(base + 2 * TDF))[c4];
    }
    __syncthreads();
    if (tid >= 196) return;

    int t0 = tid * 2, t1 = t0 + 1;
    int node0 = (br == 0) ? ((t0 / 7) * NRES + wi * 7 + (t0 % 7)) : (wi * 392 + t0);
    int node1 = (br == 0) ? ((t1 / 7) * NRES + wi * 7 + (t1 % 7)) : (wi * 392 + t1);

    const float scale = 0.2082351129f;   // 48^-0.5 * log2(e)
    ull sc2 = pack2(scale, scale);
    ull qA[24], qB[24];
    {
        const ulonglong2* qp0 = (const ulonglong2*)(g_qkv + (size_t)(b * NTOK + node0) * 1152 + colq);
        const ulonglong2* qp1 = (const ulonglong2*)(g_qkv + (size_t)(b * NTOK + node1) * 1152 + colq);
        #pragma unroll
        for (int i = 0; i < 12; i++) {
            ulonglong2 v0 = qp0[i];
            ulonglong2 v1 = qp1[i];
            qA[2*i] = fmul2(v0.x, sc2); qA[2*i+1] = fmul2(v0.y, sc2);
            qB[2*i] = fmul2(v1.x, sc2); qB[2*i+1] = fmul2(v1.y, sc2);
        }
    }
    ull OA[24], OB[24];
    #pragma unroll
    for (int i = 0; i < 24; i++) { OA[i] = 0ull; OB[i] = 0ull; }
    float mA = -1e30f, mB = -1e30f, lA = 0.f, lB = 0.f;

    for (int j0 = 0; j0 < 392; j0 += 8) {
        float sA[8], sB[8];
        #pragma unroll
        for (int jj = 0; jj < 8; jj++) {
            const ulonglong2* kr = (const ulonglong2*)(sK + (j0 + jj) * 48);
            ull a0 = 0ull, a1 = 0ull;
            #pragma unroll
            for (int i = 0; i < 12; i++) {
                ulonglong2 kv = kr[i];
                a0 = ffma2(qA[2*i],   kv.x, a0);
                a0 = ffma2(qA[2*i+1], kv.y, a0);
                a1 = ffma2(qB[2*i],   kv.x, a1);
                a1 = ffma2(qB[2*i+1], kv.y, a1);
            }
            float2 u0 = unpack2(a0);
            float2 u1 = unpack2(a1);
            sA[jj] = u0.x + u0.y;
            sB[jj] = u1.x + u1.y;
        }
        float cA = sA[0], cB = sB[0];
        #pragma unroll
        for (int jj = 1; jj < 8; jj++) {
            cA = fmaxf(cA, sA[jj]);
            cB = fmaxf(cB, sB[jj]);
        }
        if (cA > mA) {
            float corr = exp2a(mA - cA);
            ull c2 = pack2(corr, corr);
            lA *= corr;
            #pragma unroll
            for (int i = 0; i < 24; i++) OA[i] = fmul2(OA[i], c2);
            mA = cA;
        }
        if (cB > mB) {
            float corr = exp2a(mB - cB);
            ull c2 = pack2(corr, corr);
            lB *= corr;
            #pragma unroll
            for (int i = 0; i < 24; i++) OB[i] = fmul2(OB[i], c2);
            mB = cB;
        }
        #pragma unroll
        for (int jj = 0; jj < 8; jj++) {
            float pA = exp2a(sA[jj] - mA);
            float pB = exp2a(sB[jj] - mB);
            lA += pA; lB += pB;
            ull pA2 = pack2(pA, pA);
            ull pB2 = pack2(pB, pB);
            const ulonglong2* vr = (const ulonglong2*)(sV + (j0 + jj) * 48);
            #pragma unroll
            for (int i = 0; i < 12; i++) {
                ulonglong2 vv = vr[i];
                OA[2*i]   = ffma2(pA2, vv.x, OA[2*i]);
                OA[2*i+1] = ffma2(pA2, vv.y, OA[2*i+1]);
                OB[2*i]   = ffma2(pB2, vv.x, OB[2*i]);
                OB[2*i+1] = ffma2(pB2, vv.y, OB[2*i+1]);
            }
        }
    }
    {   // normalize
        float ia = 1.f / lA, ib = 1.f / lB;
        ull iva = pack2(ia, ia), ivb = pack2(ib, ib);
        #pragma unroll
        for (int i = 0; i < 24; i++) {
            OA[i] = fmul2(OA[i], iva);
            OB[i] = fmul2(OB[i], ivb);
        }
    }
    {   // fused LePE for both queries
        int Hd = br ? 7 : 56;
        int Wd = br ? 56 : 7;
        #pragma unroll
        for (int qq = 0; qq < 2; qq++) {
            int t = qq ? t1 : t0;
            ull* O = qq ? OB : OA;
            int h = t / Wd, w = t - (t / Wd) * Wd;
            #pragma unroll
            for (int dy = -1; dy <= 1; dy++) {
                int hh = h + dy;
                if (hh < 0 || hh >= Hd) continue;
                #pragma unroll
                for (int dx = -1; dx <= 1; dx++) {
                    int ww = w + dx;
                    if (ww < 0 || ww >= Wd) continue;
                    int tp = hh * Wd + ww;
                    int nb = (dy + 1) * 3 + (dx + 1);
                    const ulonglong2* vr = (const ulonglong2*)(sV + tp * 48);
                    const ulonglong2* wr = (const ulonglong2*)(swt + nb * 48);
                    #pragma unroll
                    for (int i = 0; i < 12; i++) {
                        ulonglong2 vv = vr[i];
                        ulonglong2 wv = wr[i];
                        O[2*i]   = ffma2(wv.x, vv.x, O[2*i]);
                        O[2*i+1] = ffma2(wv.y, vv.y, O[2*i+1]);
                    }
                }
            }
        }
    }
    float* opA = out + ((size_t)(b * DIMF + colq)) * NTOK + node0;
    float* opB = out + ((size_t)(b * DIMF + colq)) * NTOK + node1;
    #pragma unroll
    for (int i = 0; i < 24; i++) {
        float2 uA = unpack2(OA[i]);
        float2 uB = unpack2(OB[i]);
        float b0 = sbias[2*i], b1 = sbias[2*i + 1];
        opA[(size_t)(2*i)     * NTOK] = uA.x + b0;
        opA[(size_t)(2*i + 1) * NTOK] = uA.y + b1;
        opB[(size_t)(2*i)     * NTOK] = uB.x + b0;
        opB[(size_t)(2*i + 1) * NTOK] = uB.y + b1;
    }
}

// ---------------------------------------------------------------------------
// Lower-line flash attention v4: 128 threads (4 warps -> all 4 SMSPs; the
// 64-thread version left SMSP 2/3 idle via wid%4 mapping). Br=64, Bc=64,
// thread grid 16x8: 4 queries x 8 d-cols per thread. Same smem/pipeline.
// ---------------------------------------------------------------------------
#define FP 68   // smem row pitch (floats)
__global__ __launch_bounds__(128) void flash_dn_kernel(float* __restrict__ out)
{
    extern __shared__ float smem[];
    float* Qt = smem;               // [64 d][FP]  Qt[d][q], pre-scaled
    float* KP = smem + 64 * FP;     // [64][FP]    Kt[d][key], then Pt[key][q]
    float* Vs = smem + 128 * FP;    // [64][FP]    Vs[key][d]

    int tid = threadIdx.x;
    int tq = tid >> 3;      // 0..15 (4 queries each)
    int tk = tid & 7;       // 0..7  (8 d-cols / 8 keys each)
    int qb = blockIdx.x;    // 0..48
    int hd = blockIdx.y;    // 0..2
    int b  = blockIdx.z;    // 0..3
    int q0 = qb * 64;
    int bh = b * 3 + hd;
    const float* qTsrc = g_qT + (size_t)bh * 64 * NTOK;
    const float* kTsrc = g_kT + (size_t)bh * 64 * NTOK;

    // prologue: Q tile [64d][64q]
    #pragma unroll
    for (int i = 0; i < 8; i++) {
        int task = i * 128 + tid;
        int row = task >> 4, c4 = task & 15;
        *(float4*)&Qt[row * FP + c4 * 4] =
            *(const float4*)(qTsrc + (size_t)row * NTOK + q0 + c4 * 4);
    }

    ull O2[2][8];                 // [qpair][dcol]
    #pragma unroll
    for (int p = 0; p < 2; p++)
        #pragma unroll
        for (int d = 0; d < 8; d++) O2[p][d] = 0ull;
    float m[4], l[4];
    #pragma unroll
    for (int r = 0; r < 4; r++) { m[r] = -1e30f; l[r] = 0.f; }

    for (int kt = 0; kt < NTOK / 64; kt++) {
        int k0 = kt * 64;
        __syncthreads();   // prior tile reads done (also covers prologue)
        #pragma unroll
        for (int i = 0; i < 8; i++) {
            int task = i * 128 + tid;
            int row = task >> 4, c4 = task & 15;
            *(float4*)&KP[row * FP + c4 * 4] =
                *(const float4*)(kTsrc + (size_t)row * NTOK + k0 + c4 * 4);
            *(float4*)&Vs[row * FP + c4 * 4] =
                *(const float4*)(g_qkv + (size_t)(b * NTOK + k0 + row) * 1152 + 960 + hd * 64 + c4 * 4);
        }
        __syncthreads();

        // ---- S-GEMM: s2[qpair][key] over d ----
        ull s2[2][8];
        #pragma unroll
        for (int p = 0; p < 2; p++)
            #pragma unroll
            for (int kk = 0; kk < 8; kk++) s2[p][kk] = 0ull;
        #pragma unroll 4
        for (int k = 0; k < 64; k++) {
            ulonglong2 aa = *(const ulonglong2*)&Qt[k * FP + tq * 4];
            ull a2[2] = {aa.x, aa.y};
            float4 b0 = *(const float4*)&KP[k * FP + tk * 8];
            float4 b1 = *(const float4*)&KP[k * FP + tk * 8 + 4];
            float bk[8] = {b0.x, b0.y, b0.z, b0.w, b1.x, b1.y, b1.z, b1.w};
            #pragma unroll
            for (int kk = 0; kk < 8; kk++) {
                ull bb = pack2(bk[kk], bk[kk]);
                s2[0][kk] = ffma2(a2[0], bb, s2[0][kk]);
                s2[1][kk] = ffma2(a2[1], bb, s2[1][kk]);
            }
        }

        // ---- softmax (base-2, registers) ----
        float s[4][8];
        #pragma unroll
        for (int p = 0; p < 2; p++)
            #pragma unroll
            for (int kk = 0; kk < 8; kk++) {
                float2 u = unpack2(s2[p][kk]);
                s[2*p][kk] = u.x; s[2*p+1][kk] = u.y;
            }
        float corr[4];
        #pragma unroll
        for (int r = 0; r < 4; r++) {
            float mx = s[r][0];
            #pragma unroll
            for (int kk = 1; kk < 8; kk++) mx = fmaxf(mx, s[r][kk]);
            mx = fmaxf(mx, __shfl_xor_sync(0xFFFFFFFFu, mx, 1));
            mx = fmaxf(mx, __shfl_xor_sync(0xFFFFFFFFu, mx, 2));
            mx = fmaxf(mx, __shfl_xor_sync(0xFFFFFFFFu, mx, 4));
            float mn = fmaxf(m[r], mx);
            corr[r] = exp2a(m[r] - mn);
            m[r] = mn;
            float sum = 0.f;
            #pragma unroll
            for (int kk = 0; kk < 8; kk++) {
                float p = exp2a(s[r][kk] - mn);
                s[r][kk] = p;
                sum += p;
            }
            sum += __shfl_xor_sync(0xFFFFFFFFu, sum, 1);
            sum += __shfl_xor_sync(0xFFFFFFFFu, sum, 2);
            sum += __shfl_xor_sync(0xFFFFFFFFu, sum, 4);
            l[r] = l[r] * corr[r] + sum;
        }
        #pragma unroll
        for (int p = 0; p < 2; p++) {
            ull c2 = pack2(corr[2*p], corr[2*p+1]);
            #pragma unroll
            for (int d = 0; d < 8; d++) O2[p][d] = fmul2(O2[p][d], c2);
        }

        __syncthreads();   // all lanes done reading KP as K
        // write P^T[key][q] into KP (one float4 per key: 4 queries)
        #pragma unroll
        for (int kk = 0; kk < 8; kk++) {
            int key = tk * 8 + kk;
            *(float4*)&KP[key * FP + tq * 4] =
                make_float4(s[0][kk], s[1][kk], s[2][kk], s[3][kk]);
        }
        __syncthreads();

        // ---- PV-GEMM: O2[qpair][d] over keys ----
        #pragma unroll 4
        for (int key = 0; key < 64; key++) {
            ulonglong2 aa = *(const ulonglong2*)&KP[key * FP + tq * 4];
            ull a2[2] = {aa.x, aa.y};
            float4 v0 = *(const float4*)&Vs[key * FP + tk * 8];
            float4 v1 = *(const float4*)&Vs[key * FP + tk * 8 + 4];
            float bv[8] = {v0.x, v0.y, v0.z, v0.w, v1.x, v1.y, v1.z, v1.w};
            #pragma unroll
            for (int d = 0; d < 8; d++) {
                ull bb = pack2(bv[d], bv[d]);
                O2[0][d] = ffma2(a2[0], bb, O2[0][d]);
                O2[1][d] = ffma2(a2[1], bb, O2[1][d]);
            }
        }
    }

    // final: normalize + store (4 queries per thread -> one float4 per d)
    #pragma unroll
    for (int p = 0; p < 2; p++) {
        ull iv2 = pack2(1.f / l[2*p], 1.f / l[2*p+1]);
        #pragma unroll
        for (int d = 0; d < 8; d++) O2[p][d] = fmul2(O2[p][d], iv2);
    }
    #pragma unroll
    for (int d = 0; d < 8; d++) {
        int ch = TDF + hd * 64 + tk * 8 + d;
        float2 u0 = unpack2(O2[0][d]);
        float2 u1 = unpack2(O2[1][d]);
        float* dst = out + ((size_t)(b * DIMF + ch)) * NTOK + q0 + tq * 4;
        *(float4*)dst = make_float4(u0.x, u0.y, u1.x, u1.y);
    }
}

// ---------------------------------------------------------------------------
extern "C" void kernel_launch(void* const* d_in, const int* in_sizes, int n_in,
                              void* d_out, int out_size)
{
    const float* xa  = (const float*)d_in[0];
    const float* p1  = (const float*)d_in[1];
    const float* p2  = (const float*)d_in[2];
    const float* wu  = (const float*)d_in[3];
    const float* wd  = (const float*)d_in[4];
    const float* lw0 = (const float*)d_in[5];
    const float* lb0 = (const float*)d_in[6];
    const float* lw1 = (const float*)d_in[7];
    const float* lb1 = (const float*)d_in[8];
    float* out = (float*)d_out;

    const int cswin_smem = (2 * 392 * 48 + 9 * 48 + 48) * 4;   // 152448 B
    const int flash_smem = 3 * 64 * FP * 4;                    // 52224 B
    cudaFuncSetAttribute(cswin_kernel,
                         cudaFuncAttributeMaxDynamicSharedMemorySize, cswin_smem);
    cudaFuncSetAttribute(flash_dn_kernel,
                         cudaFuncAttributeMaxDynamicSharedMemorySize, flash_smem);

    gemm1_kernel<<<dim3(MTOT / 256, DIMF / 64), 256>>>(xa, p1, p2);
    gemm2_kernel<<<dim3(MTOT / 256, 1152 / 64), 256>>>(wu, wd);
    ktrans_kernel<<<12 * 16 * NTOK / 256, 256>>>();
    cswin_kernel<<<dim3(32, 2, 2), 256, cswin_smem>>>(lw0, lb0, lw1, lb1, out);
    flash_dn_kernel<<<dim3(NTOK / 64, 3, NB), 128, flash_smem>>>(out);
}